// round 8
// baseline (speedup 1.0000x reference)
#include <cuda_runtime.h>
#include <cuda_bf16.h>
#include <math.h>

#define HW      65536
#define BATCH   4

// ---------------- scratch (device globals; no allocation allowed) ----------
// pair channel pc <-> fp channels (c0, c1): c0 = (pc>>3)*16 + (pc&7), c1 = c0+8
__device__ unsigned g_out1p[(size_t)BATCH * 32  * HW];  //  34 MB  conv1x1#1, packed
__device__ unsigned g_catp [(size_t)BATCH * 128 * HW];  // 134 MB  cat, packed (k2 = dir*32+pc)
__device__ unsigned g_out2p[(size_t)BATCH * 32  * HW];  //  34 MB
__device__ unsigned g_a1p  [(size_t)BATCH * 16  * HW];  //  17 MB
__device__ unsigned g_a2p  [(size_t)BATCH * 16  * HW];  //  17 MB

// ---------------- helpers ---------------------------------------------------
__device__ __forceinline__ unsigned f2tf(float f) {
    unsigned u;
    asm("cvt.rna.tf32.f32 %0, %1;" : "=r"(u) : "f"(f));
    return u;
}
__device__ __forceinline__ unsigned packbf(float hi, float lo) {
    unsigned r;
    asm("cvt.rn.bf16x2.f32 %0, %1, %2;" : "=r"(r) : "f"(hi), "f"(lo));
    return r;
}
__device__ __forceinline__ float2 unpackbf(unsigned u) {
    __nv_bfloat162 h = *reinterpret_cast<__nv_bfloat162*>(&u);
    return __bfloat1622float2(h);
}
__device__ __forceinline__ void cpasync16(void* dst, const void* src) {
    unsigned d = (unsigned)__cvta_generic_to_shared(dst);
    asm volatile("cp.async.cg.shared.global [%0], [%1], 16;" :: "r"(d), "l"(src));
}

#define MMA_TF32(c, a, b0, b1)                                              \
    asm volatile("mma.sync.aligned.m16n8k8.row.col.f32.tf32.tf32.f32 "      \
        "{%0,%1,%2,%3}, {%4,%5,%6,%7}, {%8,%9}, {%0,%1,%2,%3};"             \
        : "+f"((c)[0]), "+f"((c)[1]), "+f"((c)[2]), "+f"((c)[3])            \
        : "r"((a)[0]), "r"((a)[1]), "r"((a)[2]), "r"((a)[3]),               \
          "r"(b0), "r"(b1))

#define MMA_BF16(c, a, b0, b1)                                              \
    asm volatile("mma.sync.aligned.m16n8k16.row.col.f32.bf16.bf16.f32 "     \
        "{%0,%1,%2,%3}, {%4,%5,%6,%7}, {%8,%9}, {%0,%1,%2,%3};"             \
        : "+f"((c)[0]), "+f"((c)[1]), "+f"((c)[2]), "+f"((c)[3])            \
        : "r"((a)[0]), "r"((a)[1]), "r"((a)[2]), "r"((a)[3]),               \
          "r"(b0), "r"(b1))

// ---------------------------------------------------------------------------
// TF32 GEMM stage 1 (K=64): out1p(packed) = w_in @ x.  Block M64 x N256.
// grid (256,1,4).
// ---------------------------------------------------------------------------
__global__ __launch_bounds__(256)
void k_gemm_tc64(const float* __restrict__ Wt, const float* __restrict__ X,
                 unsigned* __restrict__ Yp)
{
    __shared__ unsigned ws[64 * 36];
    __shared__ unsigned xs[32 * 264];

    const int tid  = threadIdx.x;
    const int warp = tid >> 5;
    const int lane = tid & 31;
    const int n0   = blockIdx.x * 256;
    const int b    = blockIdx.z;
    const float*  Xb = X  + (size_t)b * 64 * HW;
    unsigned*     Yb = Yp + (size_t)b * 32 * HW;

    const int mw = (warp & 1) * 32;
    const int nw = (warp >> 1) * 64;
    const int qt = lane >> 2;
    const int rt = lane & 3;

    float acc[2][8][4];
#pragma unroll
    for (int i = 0; i < 2; i++)
#pragma unroll
        for (int j = 0; j < 8; j++)
#pragma unroll
            for (int v = 0; v < 4; v++) acc[i][j][v] = 0.f;

    for (int kt = 0; kt < 64; kt += 32) {
#pragma unroll
        for (int r = 0; r < 8; r++) {
            int e  = tid + r * 256;
            int m  = e >> 5;
            int kk = e & 31;
            ws[m * 36 + kk] = f2tf(Wt[m * 64 + kt + kk]);
        }
#pragma unroll
        for (int r = 0; r < 8; r++) {
            int idx = r * 256 + tid;
            int k   = idx >> 6;
            int nf  = idx & 63;
            float4 v = *(const float4*)&Xb[(size_t)(kt + k) * HW + n0 + nf * 4];
            unsigned* d = &xs[k * 264 + nf * 4];
            d[0] = f2tf(v.x); d[1] = f2tf(v.y); d[2] = f2tf(v.z); d[3] = f2tf(v.w);
        }
        __syncthreads();

#pragma unroll
        for (int kk = 0; kk < 4; kk++) {
            const int kb = kk * 8;
            unsigned a[2][4];
#pragma unroll
            for (int mt = 0; mt < 2; mt++) {
                int mr = mw + mt * 16 + qt;
                int kc = kb + rt;
                a[mt][0] = ws[mr * 36 + kc];
                a[mt][1] = ws[(mr + 8) * 36 + kc];
                a[mt][2] = ws[mr * 36 + kc + 4];
                a[mt][3] = ws[(mr + 8) * 36 + kc + 4];
            }
#pragma unroll
            for (int nt = 0; nt < 8; nt++) {
                int col = nw + nt * 8 + qt;
                unsigned b0 = xs[(kb + rt) * 264 + col];
                unsigned b1 = xs[(kb + rt + 4) * 264 + col];
                MMA_TF32(acc[0][nt], a[0], b0, b1);
                MMA_TF32(acc[1][nt], a[1], b0, b1);
            }
        }
        __syncthreads();
    }

    // epilogue: pack rows (mr, mr+8) -> pair channel pc = (mr>>4)*8 + qt
#pragma unroll
    for (int mt = 0; mt < 2; mt++) {
        int pc = ((mw >> 4) + mt) * 8 + qt;
#pragma unroll
        for (int nt = 0; nt < 8; nt++) {
            int col = n0 + nw + nt * 8 + rt * 2;
            uint2 u;
            u.x = packbf(acc[mt][nt][2], acc[mt][nt][0]);
            u.y = packbf(acc[mt][nt][3], acc[mt][nt][1]);
            *(uint2*)&Yb[(size_t)pc * HW + col] = u;
        }
    }
}

// ---------------------------------------------------------------------------
// Fused 4-direction IRNN scans on packed pairs. Blocks 0..127 vertical,
// 128..255 horizontal. catp k2 = dir*32 + pc;  dirs up=0,right=1,down=2,left=3.
// ---------------------------------------------------------------------------
__global__ __launch_bounds__(256)
void k_scans(const unsigned* __restrict__ srcp, unsigned* __restrict__ catp,
             const float* __restrict__ w_up, const float* __restrict__ b_up,
             const float* __restrict__ w_rt, const float* __restrict__ b_rt,
             const float* __restrict__ w_dn, const float* __restrict__ b_dn,
             const float* __restrict__ w_lt, const float* __restrict__ b_lt)
{
    const bool vert = blockIdx.x < 128;
    int idx = (vert ? blockIdx.x : blockIdx.x - 128) * 256 + threadIdx.x; // [0,32768)
    int p  = idx & 255;
    int pc = (idx >> 8) & 31;
    int b  = idx >> 13;
    int c0 = ((pc >> 3) * 16) + (pc & 7);
    int c1 = c0 + 8;

    if (vert) {
        const unsigned* s = srcp + (((size_t)b * 32 + pc) << 16) + p;
        unsigned* cu = catp + (((size_t)b * 128 +      pc) << 16) + p;
        unsigned* cd = catp + (((size_t)b * 128 + 64 + pc) << 16) + p;
        float W0 = w_dn[c0], W1 = w_dn[c1], B0 = b_dn[c0], B1 = b_dn[c1];
        float h0 = 0.f, h1 = 0.f;
        for (int r = 0; r < 256; r++) {
            float2 v = unpackbf(s[r << 8]);
            h0 = fmaxf(fmaf(W0, h0, v.x + B0), 0.f);
            h1 = fmaxf(fmaf(W1, h1, v.y + B1), 0.f);
            cd[r << 8] = packbf(h1, h0);
        }
        W0 = w_up[c0]; W1 = w_up[c1]; B0 = b_up[c0]; B1 = b_up[c1];
        h0 = 0.f; h1 = 0.f;
        for (int r = 255; r >= 0; r--) {
            float2 v = unpackbf(s[r << 8]);
            h0 = fmaxf(fmaf(W0, h0, v.x + B0), 0.f);
            h1 = fmaxf(fmaf(W1, h1, v.y + B1), 0.f);
            cu[r << 8] = packbf(h1, h0);
        }
    } else {
        const unsigned* s = srcp + (((size_t)b * 32 + pc) << 16) + p * 256;
        unsigned* cr = catp + (((size_t)b * 128 + 32 + pc) << 16) + p * 256;
        unsigned* cl = catp + (((size_t)b * 128 + 96 + pc) << 16) + p * 256;
        float W0 = w_rt[c0], W1 = w_rt[c1], B0 = b_rt[c0], B1 = b_rt[c1];
        float h0 = 0.f, h1 = 0.f;
        for (int w = 0; w < 256; w++) {
            float2 v = unpackbf(s[w]);
            h0 = fmaxf(fmaf(W0, h0, v.x + B0), 0.f);
            h1 = fmaxf(fmaf(W1, h1, v.y + B1), 0.f);
            cr[w] = packbf(h1, h0);
        }
        W0 = w_lt[c0]; W1 = w_lt[c1]; B0 = b_lt[c0]; B1 = b_lt[c1];
        h0 = 0.f; h1 = 0.f;
        for (int w = 255; w >= 0; w--) {
            float2 v = unpackbf(s[w]);
            h0 = fmaxf(fmaf(W0, h0, v.x + B0), 0.f);
            h1 = fmaxf(fmaf(W1, h1, v.y + B1), 0.f);
            cl[w] = packbf(h1, h0);
        }
    }
}

// ---------------------------------------------------------------------------
// BF16 GEMM stage 3: out2p = relu(wD2 @ cat), K=256 (128 pairs).
// cp.async double-buffered B; A software-pipelined. Block M64 x N256.
// grid (256,1,4).
// ---------------------------------------------------------------------------
__global__ __launch_bounds__(256)
void k_gemm256_bf16(const float* __restrict__ Wt, const unsigned* __restrict__ Xp,
                    unsigned* __restrict__ Yp)
{
    __shared__ unsigned ws[2][64 * 20];
    __shared__ unsigned xs[2][16 * 260];

    const int tid  = threadIdx.x;
    const int warp = tid >> 5;
    const int lane = tid & 31;
    const int n0   = blockIdx.x * 256;
    const int b    = blockIdx.z;
    const unsigned* Xb = Xp + (size_t)b * 128 * HW;
    unsigned*       Yb = Yp + (size_t)b * 32 * HW;

    const int nw = warp * 32;
    const int qt = lane >> 2;
    const int rt = lane & 3;

    float acc[4][4][4];
#pragma unroll
    for (int i = 0; i < 4; i++)
#pragma unroll
        for (int j = 0; j < 4; j++)
#pragma unroll
            for (int v = 0; v < 4; v++) acc[i][j][v] = 0.f;

    // prologue
#pragma unroll
    for (int i = 0; i < 4; i++) {
        int e = tid + i * 256, m = e >> 4, l2 = e & 15;
        int dir = l2 >> 5, pcd = l2 & 31;                     // l2<16 so dir=0
        int c0 = dir * 64 + ((pcd >> 3) * 16) + (pcd & 7);
        ws[0][m * 20 + l2] = packbf(Wt[m * 256 + c0 + 8], Wt[m * 256 + c0]);
    }
#pragma unroll
    for (int j = 0; j < 4; j++) {
        int idx = tid + j * 256, row = idx >> 6, col = (idx & 63) * 4;
        cpasync16(&xs[0][row * 260 + col], Xb + (size_t)row * HW + n0 + col);
    }
    asm volatile("cp.async.commit_group;");
    asm volatile("cp.async.wait_group 0;");
    __syncthreads();

    for (int kt = 0; kt < 8; kt++) {
        const int cur = kt & 1, nxt = cur ^ 1;
        float aw0[4], aw1[4];
        if (kt < 7) {
#pragma unroll
            for (int j = 0; j < 4; j++) {
                int idx = tid + j * 256, row = idx >> 6, col = (idx & 63) * 4;
                cpasync16(&xs[nxt][row * 260 + col],
                          Xb + (size_t)((kt + 1) * 16 + row) * HW + n0 + col);
            }
            asm volatile("cp.async.commit_group;");
#pragma unroll
            for (int i = 0; i < 4; i++) {
                int e = tid + i * 256, m = e >> 4, l2 = e & 15;
                int k2g = (kt + 1) * 16 + l2;
                int dir = k2g >> 5, pcd = k2g & 31;
                int c0 = dir * 64 + ((pcd >> 3) * 16) + (pcd & 7);
                aw0[i] = Wt[m * 256 + c0]; aw1[i] = Wt[m * 256 + c0 + 8];
            }
        }

#pragma unroll
        for (int s = 0; s < 2; s++) {
            const int kb = s * 8;
            unsigned a[4][4];
#pragma unroll
            for (int mt = 0; mt < 4; mt++) {
                int m = mt * 16 + qt;
                a[mt][0] = ws[cur][m * 20 + kb + rt];
                a[mt][1] = ws[cur][(m + 8) * 20 + kb + rt];
                a[mt][2] = ws[cur][m * 20 + kb + rt + 4];
                a[mt][3] = ws[cur][(m + 8) * 20 + kb + rt + 4];
            }
#pragma unroll
            for (int nt = 0; nt < 4; nt++) {
                int col = nw + nt * 8 + qt;
                unsigned b0 = xs[cur][(kb + rt) * 260 + col];
                unsigned b1 = xs[cur][(kb + rt + 4) * 260 + col];
#pragma unroll
                for (int mt = 0; mt < 4; mt++)
                    MMA_BF16(acc[mt][nt], a[mt], b0, b1);
            }
        }

        if (kt < 7) {
#pragma unroll
            for (int i = 0; i < 4; i++) {
                int e = tid + i * 256, m = e >> 4, l2 = e & 15;
                ws[nxt][m * 20 + l2] = packbf(aw1[i], aw0[i]);
            }
            asm volatile("cp.async.wait_group 0;");
        }
        __syncthreads();
    }

    // epilogue: relu + pack rows (mr, mr+8) -> pc = mt*8 + qt
#pragma unroll
    for (int mt = 0; mt < 4; mt++) {
        int pc = mt * 8 + qt;
#pragma unroll
        for (int nt = 0; nt < 4; nt++) {
            int col = n0 + nw + nt * 8 + rt * 2;
            uint2 u;
            u.x = packbf(fmaxf(acc[mt][nt][2], 0.f), fmaxf(acc[mt][nt][0], 0.f));
            u.y = packbf(fmaxf(acc[mt][nt][3], 0.f), fmaxf(acc[mt][nt][1], 0.f));
            *(uint2*)&Yb[(size_t)pc * HW + col] = u;
        }
    }
}

// ---------------------------------------------------------------------------
// BF16 3x3 conv on packed pairs: NPAIR input pairs (CI = 2*NPAIR) -> 32 out ch
// (16 packed pairs), relu(out+bias). 2 output rows/block, cp.async staging.
// smem xs layout: [row r(4)][pair i2(8)][col 264] — col 4..259 = pixels,
// col 3 & 260 = zero halo. 16B-aligned rows AND conflict-free frag loads.
// grid (128, 1, 4).
// ---------------------------------------------------------------------------
template<int NPAIR>
__global__ __launch_bounds__(256)
void k_conv3p(const unsigned* __restrict__ inp, const float* __restrict__ wt,
              const float* __restrict__ bias, unsigned* __restrict__ outp)
{
    constexpr int CI  = NPAIR * 2;
    constexpr int NCH = NPAIR / 8;

    __shared__ unsigned xs[4 * 8 * 264];   // 33792 B
    __shared__ unsigned ws[9 * 8 * 40];    // 11520 B

    const int h0    = blockIdx.x * 2;
    const int b     = blockIdx.z;
    const int tid   = threadIdx.x;
    const int warp  = tid >> 5;
    const int lane  = tid & 31;
    const int rw    = warp >> 2;           // output row 0/1
    const int strip = (warp & 3) * 64;
    const int qt    = lane >> 2;
    const int rt    = lane & 3;

    const unsigned* inb = inp + (size_t)b * NPAIR * HW;

    // zero halo columns once
    if (tid < 64) {
        int i2 = tid & 7, r = (tid >> 3) & 3, side = tid >> 5;
        xs[(r * 8 + i2) * 264 + (side ? 260 : 3)] = 0u;
    }

    float acc[2][8][4];
#pragma unroll
    for (int i = 0; i < 2; i++)
#pragma unroll
        for (int j = 0; j < 8; j++)
#pragma unroll
            for (int v = 0; v < 4; v++) acc[i][j][v] = 0.f;

    for (int ch = 0; ch < NCH; ch++) {
        // stage input: 8 pairs x 4 rows x 256 px via cp.async 16B
#pragma unroll
        for (int j = 0; j < 8; j++) {
            int e   = tid + j * 256;
            int i2  = e >> 8;
            int r   = (e >> 6) & 3;
            int blk = e & 63;
            int hh  = h0 + r - 1;
            unsigned* dst = &xs[(r * 8 + i2) * 264 + 4 + blk * 4];
            if ((unsigned)hh < 256u)
                cpasync16(dst, inb + (size_t)(ch * 8 + i2) * HW + hh * 256 + blk * 4);
            else
                *(uint4*)dst = make_uint4(0, 0, 0, 0);
        }
        asm volatile("cp.async.commit_group;");
        // stage weights: ws[(tap*8+i2)*40 + o] = pack(wt[o][c1][tap], wt[o][c0][tap])
        for (int e = tid; e < 9 * 8 * 32; e += 256) {
            int tap = e >> 8;
            int i2  = (e >> 5) & 7;
            int o   = e & 31;
            int pg  = ch * 8 + i2;
            int c0  = ((pg >> 3) * 16) + (pg & 7);
            const float* p = wt + ((size_t)o * CI + c0) * 9 + tap;
            ws[(tap * 8 + i2) * 40 + o] = packbf(p[72], p[0]);
        }
        asm volatile("cp.async.wait_group 0;");
        __syncthreads();

#pragma unroll
        for (int tap = 0; tap < 9; tap++) {
            const int r = tap / 3, c = tap % 3;
            unsigned a[2][4];
#pragma unroll
            for (int mt = 0; mt < 2; mt++) {
                int o = mt * 16 + qt;
                a[mt][0] = ws[(tap * 8 + rt) * 40 + o];
                a[mt][1] = ws[(tap * 8 + rt) * 40 + o + 8];
                a[mt][2] = ws[(tap * 8 + rt + 4) * 40 + o];
                a[mt][3] = ws[(tap * 8 + rt + 4) * 40 + o + 8];
            }
            const int rowidx = rw + r;
#pragma unroll
            for (int nt = 0; nt < 8; nt++) {
                int col = strip + nt * 8 + qt + c + 3;
                unsigned b0 = xs[(rowidx * 8 + rt) * 264 + col];
                unsigned b1 = xs[(rowidx * 8 + rt + 4) * 264 + col];
                MMA_BF16(acc[0][nt], a[0], b0, b1);
                MMA_BF16(acc[1][nt], a[1], b0, b1);
            }
        }
        __syncthreads();
    }

    // epilogue: bias + relu, pack (o, o+8) -> pc = mt*8 + qt
    const int orow = (h0 + rw) * 256;
#pragma unroll
    for (int mt = 0; mt < 2; mt++) {
        int o   = mt * 16 + qt;
        int pc  = mt * 8 + qt;
        float bv0 = bias[o];
        float bv1 = bias[o + 8];
#pragma unroll
        for (int nt = 0; nt < 8; nt++) {
            int col = strip + nt * 8 + rt * 2;
            uint2 u;
            u.x = packbf(fmaxf(acc[mt][nt][2] + bv1, 0.f),
                         fmaxf(acc[mt][nt][0] + bv0, 0.f));
            u.y = packbf(fmaxf(acc[mt][nt][3] + bv1, 0.f),
                         fmaxf(acc[mt][nt][1] + bv0, 0.f));
            *(uint2*)&outp[((size_t)(b * 16 + pc)) * HW + orow + col] = u;
        }
    }
}

// ---------------------------------------------------------------------------
// Final: a = a3_w . a2 + a3_b ; weight = sigmoid(a) ; out = relu(x * weight)
// a2 packed; 4 pixels per thread.
// ---------------------------------------------------------------------------
__global__ __launch_bounds__(256)
void k_final4(const unsigned* __restrict__ a2p, const float* __restrict__ a3w,
              const float* __restrict__ a3b, const float* __restrict__ x,
              float* __restrict__ out)
{
    int t   = blockIdx.x * 256 + threadIdx.x;    // [0, 65536)
    int b   = t >> 14;
    int hw  = (t & 16383) * 4;

    const unsigned* ab = a2p + ((size_t)b * 16) * HW + hw;
    float bv = a3b[0];
    float4 s = {bv, bv, bv, bv};
#pragma unroll
    for (int pc = 0; pc < 16; pc++) {
        int c0 = ((pc >> 3) * 16) + (pc & 7);
        float w0 = a3w[c0], w1 = a3w[c0 + 8];
        uint4 u = *(const uint4*)&ab[(size_t)pc * HW];
        float2 v0 = unpackbf(u.x), v1 = unpackbf(u.y);
        float2 v2 = unpackbf(u.z), v3 = unpackbf(u.w);
        s.x = fmaf(w0, v0.x, fmaf(w1, v0.y, s.x));
        s.y = fmaf(w0, v1.x, fmaf(w1, v1.y, s.y));
        s.z = fmaf(w0, v2.x, fmaf(w1, v2.y, s.z));
        s.w = fmaf(w0, v3.x, fmaf(w1, v3.y, s.w));
    }
    float4 g;
    g.x = 1.f / (1.f + expf(-s.x));
    g.y = 1.f / (1.f + expf(-s.y));
    g.z = 1.f / (1.f + expf(-s.z));
    g.w = 1.f / (1.f + expf(-s.w));

    const float* xb = x   + ((size_t)b * 64) * HW + hw;
    float*       ob = out + ((size_t)b * 64) * HW + hw;
#pragma unroll 8
    for (int c = 0; c < 64; c++) {
        float4 v = *(const float4*)&xb[(size_t)c * HW];
        float4 r;
        r.x = fmaxf(v.x * g.x, 0.f);
        r.y = fmaxf(v.y * g.y, 0.f);
        r.z = fmaxf(v.z * g.z, 0.f);
        r.w = fmaxf(v.w * g.w, 0.f);
        *(float4*)&ob[(size_t)c * HW] = r;
    }
}

// ---------------------------------------------------------------------------
extern "C" void kernel_launch(void* const* d_in, const int* in_sizes, int n_in,
                              void* d_out, int out_size)
{
    const float* x       = (const float*)d_in[0];
    const float* w_in    = (const float*)d_in[1];
    const float* w_up    = (const float*)d_in[2];
    const float* b_up    = (const float*)d_in[3];
    const float* w_right = (const float*)d_in[4];
    const float* b_right = (const float*)d_in[5];
    const float* w_down  = (const float*)d_in[6];
    const float* b_down  = (const float*)d_in[7];
    const float* w_left  = (const float*)d_in[8];
    const float* b_left  = (const float*)d_in[9];
    const float* wD2     = (const float*)d_in[10];
    const float* a1_w    = (const float*)d_in[11];
    const float* a1_b    = (const float*)d_in[12];
    const float* a2_w    = (const float*)d_in[13];
    const float* a2_b    = (const float*)d_in[14];
    const float* a3_w    = (const float*)d_in[15];
    const float* a3_b    = (const float*)d_in[16];
    float* out = (float*)d_out;

    unsigned *p_out1p, *p_catp, *p_out2p, *p_a1p, *p_a2p;
    cudaGetSymbolAddress((void**)&p_out1p, g_out1p);
    cudaGetSymbolAddress((void**)&p_catp,  g_catp);
    cudaGetSymbolAddress((void**)&p_out2p, g_out2p);
    cudaGetSymbolAddress((void**)&p_a1p,   g_a1p);
    cudaGetSymbolAddress((void**)&p_a2p,   g_a2p);

    dim3 gGemm(HW / 256, 1, BATCH);      // (256,1,4)
    dim3 gConv(128, 1, BATCH);

    // 1) out1p = conv1x1(x, w_in)   (TF32 MMA, packed bf16 out)
    k_gemm_tc64<<<gGemm, 256>>>(w_in, x, p_out1p);

    // 2) fused 4-direction scans (packed in, packed out)
    k_scans<<<256, 256>>>(p_out1p, p_catp,
                          w_up, b_up, w_right, b_right,
                          w_down, b_down, w_left, b_left);

    // 3) out2p = relu(conv1x1(cat, wD2))   bf16 MMA, cp.async pipelined
    k_gemm256_bf16<<<gGemm, 256>>>(wD2, p_catp, p_out2p);

    // 4) a1p = relu(conv3x3(out2, a1_w) + a1_b)
    k_conv3p<32><<<gConv, 256>>>(p_out2p, a1_w, a1_b, p_a1p);

    // 5) a2p = relu(conv3x3(a1, a2_w) + a2_b)
    k_conv3p<16><<<gConv, 256>>>(p_a1p, a2_w, a2_b, p_a2p);

    // 6) out = relu(x * sigmoid(a3_w . a2 + a3_b))
    k_final4<<<256, 256>>>(p_a2p, a3_w, a3_b, x, out);
}

// round 9
// speedup vs baseline: 1.7862x; 1.7862x over previous
#include <cuda_runtime.h>
#include <cuda_bf16.h>
#include <math.h>

#define HW      65536
#define BATCH   4

// ---------------- scratch (device globals; no allocation allowed) ----------
// pair channel pc <-> fp channels (c0, c1): c0 = (pc>>3)*16 + (pc&7), c1 = c0+8
__device__ unsigned g_out1p[(size_t)BATCH * 32  * HW];  //  34 MB
__device__ unsigned g_catp [(size_t)BATCH * 128 * HW];  // 134 MB (k2 = dir*32+pc)
__device__ unsigned g_out2p[(size_t)BATCH * 32  * HW];  //  34 MB
__device__ unsigned g_a1p  [(size_t)BATCH * 16  * HW];  //  17 MB
__device__ unsigned g_a2p  [(size_t)BATCH * 16  * HW];  //  17 MB

// ---------------- helpers ---------------------------------------------------
__device__ __forceinline__ unsigned f2tf(float f) {
    unsigned u;
    asm("cvt.rna.tf32.f32 %0, %1;" : "=r"(u) : "f"(f));
    return u;
}
__device__ __forceinline__ unsigned packbf(float hi, float lo) {
    unsigned r;
    asm("cvt.rn.bf16x2.f32 %0, %1, %2;" : "=r"(r) : "f"(hi), "f"(lo));
    return r;
}
__device__ __forceinline__ float2 unpackbf(unsigned u) {
    __nv_bfloat162 h = *reinterpret_cast<__nv_bfloat162*>(&u);
    return __bfloat1622float2(h);
}
__device__ __forceinline__ void cpasync16(void* dst, const void* src) {
    unsigned d = (unsigned)__cvta_generic_to_shared(dst);
    asm volatile("cp.async.cg.shared.global [%0], [%1], 16;" :: "r"(d), "l"(src));
}

#define MMA_TF32(c, a, b0, b1)                                              \
    asm volatile("mma.sync.aligned.m16n8k8.row.col.f32.tf32.tf32.f32 "      \
        "{%0,%1,%2,%3}, {%4,%5,%6,%7}, {%8,%9}, {%0,%1,%2,%3};"             \
        : "+f"((c)[0]), "+f"((c)[1]), "+f"((c)[2]), "+f"((c)[3])            \
        : "r"((a)[0]), "r"((a)[1]), "r"((a)[2]), "r"((a)[3]),               \
          "r"(b0), "r"(b1))

#define MMA_BF16(c, a, b0, b1)                                              \
    asm volatile("mma.sync.aligned.m16n8k16.row.col.f32.bf16.bf16.f32 "     \
        "{%0,%1,%2,%3}, {%4,%5,%6,%7}, {%8,%9}, {%0,%1,%2,%3};"             \
        : "+f"((c)[0]), "+f"((c)[1]), "+f"((c)[2]), "+f"((c)[3])            \
        : "r"((a)[0]), "r"((a)[1]), "r"((a)[2]), "r"((a)[3]),               \
          "r"(b0), "r"(b1))

// ---------------------------------------------------------------------------
// TF32 GEMM stage 1 (K=64): out1p(packed) = w_in @ x.  (unchanged)
// ---------------------------------------------------------------------------
__global__ __launch_bounds__(256)
void k_gemm_tc64(const float* __restrict__ Wt, const float* __restrict__ X,
                 unsigned* __restrict__ Yp)
{
    __shared__ unsigned ws[64 * 36];
    __shared__ unsigned xs[32 * 264];

    const int tid  = threadIdx.x;
    const int warp = tid >> 5;
    const int lane = tid & 31;
    const int n0   = blockIdx.x * 256;
    const int b    = blockIdx.z;
    const float*  Xb = X  + (size_t)b * 64 * HW;
    unsigned*     Yb = Yp + (size_t)b * 32 * HW;

    const int mw = (warp & 1) * 32;
    const int nw = (warp >> 1) * 64;
    const int qt = lane >> 2;
    const int rt = lane & 3;

    float acc[2][8][4];
#pragma unroll
    for (int i = 0; i < 2; i++)
#pragma unroll
        for (int j = 0; j < 8; j++)
#pragma unroll
            for (int v = 0; v < 4; v++) acc[i][j][v] = 0.f;

    for (int kt = 0; kt < 64; kt += 32) {
#pragma unroll
        for (int r = 0; r < 8; r++) {
            int e  = tid + r * 256;
            int m  = e >> 5;
            int kk = e & 31;
            ws[m * 36 + kk] = f2tf(Wt[m * 64 + kt + kk]);
        }
#pragma unroll
        for (int r = 0; r < 8; r++) {
            int idx = r * 256 + tid;
            int k   = idx >> 6;
            int nf  = idx & 63;
            float4 v = *(const float4*)&Xb[(size_t)(kt + k) * HW + n0 + nf * 4];
            unsigned* d = &xs[k * 264 + nf * 4];
            d[0] = f2tf(v.x); d[1] = f2tf(v.y); d[2] = f2tf(v.z); d[3] = f2tf(v.w);
        }
        __syncthreads();

#pragma unroll
        for (int kk = 0; kk < 4; kk++) {
            const int kb = kk * 8;
            unsigned a[2][4];
#pragma unroll
            for (int mt = 0; mt < 2; mt++) {
                int mr = mw + mt * 16 + qt;
                int kc = kb + rt;
                a[mt][0] = ws[mr * 36 + kc];
                a[mt][1] = ws[(mr + 8) * 36 + kc];
                a[mt][2] = ws[mr * 36 + kc + 4];
                a[mt][3] = ws[(mr + 8) * 36 + kc + 4];
            }
#pragma unroll
            for (int nt = 0; nt < 8; nt++) {
                int col = nw + nt * 8 + qt;
                unsigned b0 = xs[(kb + rt) * 264 + col];
                unsigned b1 = xs[(kb + rt + 4) * 264 + col];
                MMA_TF32(acc[0][nt], a[0], b0, b1);
                MMA_TF32(acc[1][nt], a[1], b0, b1);
            }
        }
        __syncthreads();
    }

#pragma unroll
    for (int mt = 0; mt < 2; mt++) {
        int pc = ((mw >> 4) + mt) * 8 + qt;
#pragma unroll
        for (int nt = 0; nt < 8; nt++) {
            int col = n0 + nw + nt * 8 + rt * 2;
            uint2 u;
            u.x = packbf(acc[mt][nt][2], acc[mt][nt][0]);
            u.y = packbf(acc[mt][nt][3], acc[mt][nt][1]);
            *(uint2*)&Yb[(size_t)pc * HW + col] = u;
        }
    }
}

// ---------------------------------------------------------------------------
// 4-direction IRNN scans, one pass per block (fwd/bwd split => 2x parallelism).
// 512 blocks: [0,128) down, [128,256) up, [256,384) right, [384,512) left.
// Prefetched + unrolled. catp k2 = dir*32+pc; dirs up=0,right=1,down=2,left=3.
// ---------------------------------------------------------------------------
__global__ __launch_bounds__(256)
void k_scans4(const unsigned* __restrict__ srcp, unsigned* __restrict__ catp,
              const float* __restrict__ w_up, const float* __restrict__ b_up,
              const float* __restrict__ w_rt, const float* __restrict__ b_rt,
              const float* __restrict__ w_dn, const float* __restrict__ b_dn,
              const float* __restrict__ w_lt, const float* __restrict__ b_lt)
{
    const int dir = blockIdx.x >> 7;
    const int blk = blockIdx.x & 127;
    const int tid = threadIdx.x;
    const int pc  = blk & 31;
    const int b   = blk >> 5;
    const int c0  = ((pc >> 3) * 16) + (pc & 7);
    const int c1  = c0 + 8;

    const float *wv, *bv;
    int k2off; bool vert, fwd;
    if (dir == 0)      { wv = w_dn; bv = b_dn; k2off = 64; vert = true;  fwd = true;  }
    else if (dir == 1) { wv = w_up; bv = b_up; k2off = 0;  vert = true;  fwd = false; }
    else if (dir == 2) { wv = w_rt; bv = b_rt; k2off = 32; vert = false; fwd = true;  }
    else               { wv = w_lt; bv = b_lt; k2off = 96; vert = false; fwd = false; }

    const float W0 = wv[c0], W1 = wv[c1], B0 = bv[c0], B1 = bv[c1];

    int off  = vert ? tid : tid * 256;
    int step = vert ? 256 : 1;
    if (!fwd) { off += step * 255; step = -step; }

    const unsigned* sp = srcp + (((size_t)b * 32 + pc) << 16) + off;
    unsigned*       dp = catp + (((size_t)b * 128 + k2off + pc) << 16) + off;

    float h0 = 0.f, h1 = 0.f;
    unsigned v = *sp;
    sp += step;
#pragma unroll 8
    for (int i = 0; i < 256; i++) {
        unsigned vn = 0;
        if (i < 255) vn = *sp;          // prefetch: independent of the fma chain
        sp += step;
        float2 f = unpackbf(v);
        h0 = fmaxf(fmaf(W0, h0, f.x + B0), 0.f);
        h1 = fmaxf(fmaf(W1, h1, f.y + B1), 0.f);
        *dp = packbf(h1, h0);
        dp += step;
        v = vn;
    }
}

// ---------------------------------------------------------------------------
// BF16 GEMM stage 3: out2p = relu(wD2 @ cat), K=256 (128 pairs).
// Full A resident in smem (stride 132, conflict-free), 3-stage cp.async ring
// for B (stride 264 -> conflict-free frag loads). Dynamic smem 84.5 KB.
// ---------------------------------------------------------------------------
#define G256_WS   (64 * 132)            // 8448 words
#define G256_XSLOT (16 * 264)           // 4224 words
#define G256_SMEM ((G256_WS + 3 * G256_XSLOT) * 4)

__global__ __launch_bounds__(256)
void k_gemm256_bf16(const float* __restrict__ Wt, const unsigned* __restrict__ Xp,
                    unsigned* __restrict__ Yp)
{
    extern __shared__ unsigned dsm[];
    unsigned* wsf = dsm;                // [64][132]
    unsigned* xsp = dsm + G256_WS;      // 3 slots of [16][264]

    const int tid  = threadIdx.x;
    const int warp = tid >> 5;
    const int lane = tid & 31;
    const int n0   = blockIdx.x * 256;
    const int b    = blockIdx.z;
    const unsigned* Xb = Xp + (size_t)b * 128 * HW;
    unsigned*       Yb = Yp + (size_t)b * 32 * HW;

    const int nw = warp * 32;
    const int qt = lane >> 2;
    const int rt = lane & 3;

    // stage B chunks 0,1 first (overlaps with A packing below)
#pragma unroll
    for (int c = 0; c < 2; c++) {
#pragma unroll
        for (int j = 0; j < 4; j++) {
            int idx = tid + j * 256, row = idx >> 6, col4 = (idx & 63) * 4;
            cpasync16(&xsp[c * G256_XSLOT + row * 264 + col4],
                      Xb + (size_t)(c * 16 + row) * HW + n0 + col4);
        }
        asm volatile("cp.async.commit_group;");
    }

    // pack full A: wsf[m][l2] = bf16x2(Wt[m][c0], Wt[m][c0+8])
#pragma unroll
    for (int i = 0; i < 32; i++) {
        int e = tid + i * 256;
        int m = e >> 7, l2 = e & 127;
        int d2 = l2 >> 5, pcd = l2 & 31;
        int cc = d2 * 64 + ((pcd >> 3) * 16) + (pcd & 7);
        wsf[m * 132 + l2] = packbf(Wt[m * 256 + cc + 8], Wt[m * 256 + cc]);
    }

    float acc[4][4][4];
#pragma unroll
    for (int i = 0; i < 4; i++)
#pragma unroll
        for (int j = 0; j < 4; j++)
#pragma unroll
            for (int v = 0; v < 4; v++) acc[i][j][v] = 0.f;

    for (int kt = 0; kt < 8; kt++) {
        __syncthreads();                      // protect ring slot reuse
        if (kt + 2 < 8) {
            int sl = (kt + 2) % 3;
#pragma unroll
            for (int j = 0; j < 4; j++) {
                int idx = tid + j * 256, row = idx >> 6, col4 = (idx & 63) * 4;
                cpasync16(&xsp[sl * G256_XSLOT + row * 264 + col4],
                          Xb + (size_t)((kt + 2) * 16 + row) * HW + n0 + col4);
            }
            asm volatile("cp.async.commit_group;");
        }
        if (kt < 6)      asm volatile("cp.async.wait_group 2;");
        else if (kt == 6) asm volatile("cp.async.wait_group 1;");
        else              asm volatile("cp.async.wait_group 0;");
        __syncthreads();

        const unsigned* xc = xsp + (kt % 3) * G256_XSLOT;
        const int kg = kt * 16;
#pragma unroll
        for (int s = 0; s < 2; s++) {
            const int kb = s * 8;
            unsigned a[4][4];
#pragma unroll
            for (int mt = 0; mt < 4; mt++) {
                int m = mt * 16 + qt;
                int k2 = kg + kb + rt;
                a[mt][0] = wsf[m * 132 + k2];
                a[mt][1] = wsf[(m + 8) * 132 + k2];
                a[mt][2] = wsf[m * 132 + k2 + 4];
                a[mt][3] = wsf[(m + 8) * 132 + k2 + 4];
            }
#pragma unroll
            for (int nt = 0; nt < 4; nt++) {
                int col = nw + nt * 8 + qt;
                unsigned b0 = xc[(kb + rt) * 264 + col];
                unsigned b1 = xc[(kb + rt + 4) * 264 + col];
#pragma unroll
                for (int mt = 0; mt < 4; mt++)
                    MMA_BF16(acc[mt][nt], a[mt], b0, b1);
            }
        }
    }

    // epilogue: relu + pack rows (m, m+8) -> pc = mt*8 + qt
#pragma unroll
    for (int mt = 0; mt < 4; mt++) {
        int pc = mt * 8 + qt;
#pragma unroll
        for (int nt = 0; nt < 4; nt++) {
            int col = n0 + nw + nt * 8 + rt * 2;
            uint2 u;
            u.x = packbf(fmaxf(acc[mt][nt][2], 0.f), fmaxf(acc[mt][nt][0], 0.f));
            u.y = packbf(fmaxf(acc[mt][nt][3], 0.f), fmaxf(acc[mt][nt][1], 0.f));
            *(uint2*)&Yb[(size_t)pc * HW + col] = u;
        }
    }
}

// ---------------------------------------------------------------------------
// BF16 3x3 conv on packed pairs, double-buffered channel-chunk pipeline.
// chunk = 8 pairs (16 ch). xs[2][4 rows][8 pairs][264], ws[2][9][8][40].
// Dynamic smem 90.6 KB -> 2 CTA/SM. grid (128,1,4).
// ---------------------------------------------------------------------------
#define CONV_XSLOT (4 * 8 * 264)        // 8448 words
#define CONV_WSLOT (9 * 8 * 40)         // 2880 words
#define CONV_SMEM  ((2 * CONV_XSLOT + 2 * CONV_WSLOT) * 4)

template<int NPAIR>
__global__ __launch_bounds__(256)
void k_conv3p(const unsigned* __restrict__ inp, const float* __restrict__ wt,
              const float* __restrict__ bias, unsigned* __restrict__ outp)
{
    constexpr int CI  = NPAIR * 2;
    constexpr int NCH = NPAIR / 8;

    extern __shared__ unsigned dsm[];
    unsigned* xsb = dsm;                       // 2 x CONV_XSLOT
    unsigned* wsb = dsm + 2 * CONV_XSLOT;      // 2 x CONV_WSLOT

    const int h0    = blockIdx.x * 2;
    const int b     = blockIdx.z;
    const int tid   = threadIdx.x;
    const int warp  = tid >> 5;
    const int lane  = tid & 31;
    const int rw    = warp >> 2;               // output row 0/1
    const int strip = (warp & 3) * 64;
    const int qt    = lane >> 2;
    const int rt    = lane & 3;

    const unsigned* inb = inp + (size_t)b * NPAIR * HW;

    // zero halo columns (cols 3 & 260) in both buffers, once
    if (tid < 128) {
        int buf = tid >> 6, rem = tid & 63;
        int side = rem >> 5, rr = (rem >> 3) & 3, i2 = rem & 7;
        xsb[buf * CONV_XSLOT + (rr * 8 + i2) * 264 + (side ? 260 : 3)] = 0u;
    }

    float acc[2][8][4];
#pragma unroll
    for (int i = 0; i < 2; i++)
#pragma unroll
        for (int j = 0; j < 8; j++)
#pragma unroll
            for (int v = 0; v < 4; v++) acc[i][j][v] = 0.f;

    // ---- staging lambdas (macro-style) ----
#define STAGE_X(CH, XD)                                                       \
    {                                                                         \
        unsigned* xd = (XD);                                                  \
        _Pragma("unroll")                                                     \
        for (int j = 0; j < 8; j++) {                                         \
            int e  = tid + j * 256;                                           \
            int i2 = e >> 8;                                                  \
            int r  = (e >> 6) & 3;                                            \
            int bk = e & 63;                                                  \
            int hh = h0 + r - 1;                                              \
            unsigned* dst = &xd[(r * 8 + i2) * 264 + 4 + bk * 4];             \
            if ((unsigned)hh < 256u)                                          \
                cpasync16(dst, inb + (size_t)((CH) * 8 + i2) * HW + hh * 256 + bk * 4); \
            else                                                              \
                *(uint4*)dst = make_uint4(0, 0, 0, 0);                        \
        }                                                                     \
        asm volatile("cp.async.commit_group;");                               \
    }

#define STAGE_W(CH, WD)                                                       \
    {                                                                         \
        unsigned* wd = (WD);                                                  \
        for (int e = tid; e < 9 * 8 * 32; e += 256) {                         \
            int tap = e >> 8;                                                 \
            int i2  = (e >> 5) & 7;                                           \
            int o   = e & 31;                                                 \
            int pg  = (CH) * 8 + i2;                                          \
            int cc  = ((pg >> 3) * 16) + (pg & 7);                            \
            const float* p = wt + ((size_t)o * CI + cc) * 9 + tap;            \
            wd[(tap * 8 + i2) * 40 + o] = packbf(p[72], p[0]);                \
        }                                                                     \
    }

    // prologue: chunk 0
    STAGE_X(0, xsb + 0);
    STAGE_W(0, wsb + 0);

    for (int ch = 0; ch < NCH; ch++) {
        const int cur = ch & 1, nxt = cur ^ 1;
        __syncthreads();                        // protect nxt buffers (prev compute)
        if (ch + 1 < NCH) {
            STAGE_X(ch + 1, xsb + nxt * CONV_XSLOT);
            STAGE_W(ch + 1, wsb + nxt * CONV_WSLOT);
            asm volatile("cp.async.wait_group 1;");
        } else {
            asm volatile("cp.async.wait_group 0;");
        }
        __syncthreads();                        // cur buffers visible

        const unsigned* xc = xsb + cur * CONV_XSLOT;
        const unsigned* wc = wsb + cur * CONV_WSLOT;
#pragma unroll
        for (int tap = 0; tap < 9; tap++) {
            const int r = tap / 3, c = tap % 3;
            unsigned a[2][4];
#pragma unroll
            for (int mt = 0; mt < 2; mt++) {
                int o = mt * 16 + qt;
                a[mt][0] = wc[(tap * 8 + rt) * 40 + o];
                a[mt][1] = wc[(tap * 8 + rt) * 40 + o + 8];
                a[mt][2] = wc[(tap * 8 + rt + 4) * 40 + o];
                a[mt][3] = wc[(tap * 8 + rt + 4) * 40 + o + 8];
            }
            const int rowidx = rw + r;
#pragma unroll
            for (int nt = 0; nt < 8; nt++) {
                int col = strip + nt * 8 + qt + c + 3;
                unsigned b0 = xc[(rowidx * 8 + rt) * 264 + col];
                unsigned b1 = xc[(rowidx * 8 + rt + 4) * 264 + col];
                MMA_BF16(acc[0][nt], a[0], b0, b1);
                MMA_BF16(acc[1][nt], a[1], b0, b1);
            }
        }
    }
#undef STAGE_X
#undef STAGE_W

    // epilogue: bias + relu, pack (o, o+8) -> pc = mt*8 + qt
    const int orow = (h0 + rw) * 256;
#pragma unroll
    for (int mt = 0; mt < 2; mt++) {
        int o   = mt * 16 + qt;
        int pc  = mt * 8 + qt;
        float bv0 = bias[o];
        float bv1 = bias[o + 8];
#pragma unroll
        for (int nt = 0; nt < 8; nt++) {
            int col = strip + nt * 8 + rt * 2;
            uint2 u;
            u.x = packbf(fmaxf(acc[mt][nt][2] + bv1, 0.f),
                         fmaxf(acc[mt][nt][0] + bv0, 0.f));
            u.y = packbf(fmaxf(acc[mt][nt][3] + bv1, 0.f),
                         fmaxf(acc[mt][nt][1] + bv0, 0.f));
            *(uint2*)&outp[((size_t)(b * 16 + pc)) * HW + orow + col] = u;
        }
    }
}

// ---------------------------------------------------------------------------
// Final: a = a3_w . a2 + a3_b ; weight = sigmoid(a) ; out = relu(x * weight)
// ---------------------------------------------------------------------------
__global__ __launch_bounds__(256)
void k_final4(const unsigned* __restrict__ a2p, const float* __restrict__ a3w,
              const float* __restrict__ a3b, const float* __restrict__ x,
              float* __restrict__ out)
{
    int t   = blockIdx.x * 256 + threadIdx.x;
    int b   = t >> 14;
    int hw  = (t & 16383) * 4;

    const unsigned* ab = a2p + ((size_t)b * 16) * HW + hw;
    float bv = a3b[0];
    float4 s = {bv, bv, bv, bv};
#pragma unroll
    for (int pc = 0; pc < 16; pc++) {
        int c0 = ((pc >> 3) * 16) + (pc & 7);
        float w0 = a3w[c0], w1 = a3w[c0 + 8];
        uint4 u = *(const uint4*)&ab[(size_t)pc * HW];
        float2 v0 = unpackbf(u.x), v1 = unpackbf(u.y);
        float2 v2 = unpackbf(u.z), v3 = unpackbf(u.w);
        s.x = fmaf(w0, v0.x, fmaf(w1, v0.y, s.x));
        s.y = fmaf(w0, v1.x, fmaf(w1, v1.y, s.y));
        s.z = fmaf(w0, v2.x, fmaf(w1, v2.y, s.z));
        s.w = fmaf(w0, v3.x, fmaf(w1, v3.y, s.w));
    }
    float4 g;
    g.x = 1.f / (1.f + expf(-s.x));
    g.y = 1.f / (1.f + expf(-s.y));
    g.z = 1.f / (1.f + expf(-s.z));
    g.w = 1.f / (1.f + expf(-s.w));

    const float* xb = x   + ((size_t)b * 64) * HW + hw;
    float*       ob = out + ((size_t)b * 64) * HW + hw;
#pragma unroll 8
    for (int c = 0; c < 64; c++) {
        float4 v = *(const float4*)&xb[(size_t)c * HW];
        float4 r;
        r.x = fmaxf(v.x * g.x, 0.f);
        r.y = fmaxf(v.y * g.y, 0.f);
        r.z = fmaxf(v.z * g.z, 0.f);
        r.w = fmaxf(v.w * g.w, 0.f);
        *(float4*)&ob[(size_t)c * HW] = r;
    }
}

// ---------------------------------------------------------------------------
extern "C" void kernel_launch(void* const* d_in, const int* in_sizes, int n_in,
                              void* d_out, int out_size)
{
    const float* x       = (const float*)d_in[0];
    const float* w_in    = (const float*)d_in[1];
    const float* w_up    = (const float*)d_in[2];
    const float* b_up    = (const float*)d_in[3];
    const float* w_right = (const float*)d_in[4];
    const float* b_right = (const float*)d_in[5];
    const float* w_down  = (const float*)d_in[6];
    const float* b_down  = (const float*)d_in[7];
    const float* w_left  = (const float*)d_in[8];
    const float* b_left  = (const float*)d_in[9];
    const float* wD2     = (const float*)d_in[10];
    const float* a1_w    = (const float*)d_in[11];
    const float* a1_b    = (const float*)d_in[12];
    const float* a2_w    = (const float*)d_in[13];
    const float* a2_b    = (const float*)d_in[14];
    const float* a3_w    = (const float*)d_in[15];
    const float* a3_b    = (const float*)d_in[16];
    float* out = (float*)d_out;

    unsigned *p_out1p, *p_catp, *p_out2p, *p_a1p, *p_a2p;
    cudaGetSymbolAddress((void**)&p_out1p, g_out1p);
    cudaGetSymbolAddress((void**)&p_catp,  g_catp);
    cudaGetSymbolAddress((void**)&p_out2p, g_out2p);
    cudaGetSymbolAddress((void**)&p_a1p,   g_a1p);
    cudaGetSymbolAddress((void**)&p_a2p,   g_a2p);

    // opt-in to >48KB dynamic smem (attribute set is idempotent, capture-safe)
    cudaFuncSetAttribute(k_gemm256_bf16,
                         cudaFuncAttributeMaxDynamicSharedMemorySize, G256_SMEM);
    cudaFuncSetAttribute(k_conv3p<32>,
                         cudaFuncAttributeMaxDynamicSharedMemorySize, CONV_SMEM);
    cudaFuncSetAttribute(k_conv3p<16>,
                         cudaFuncAttributeMaxDynamicSharedMemorySize, CONV_SMEM);

    dim3 gGemm(HW / 256, 1, BATCH);      // (256,1,4)
    dim3 gConv(128, 1, BATCH);

    // 1) out1p = conv1x1(x, w_in)   (TF32 MMA, packed bf16 out)
    k_gemm_tc64<<<gGemm, 256>>>(w_in, x, p_out1p);

    // 2) 4-direction scans, fwd/bwd split (512 independent blocks)
    k_scans4<<<512, 256>>>(p_out1p, p_catp,
                           w_up, b_up, w_right, b_right,
                           w_down, b_down, w_left, b_left);

    // 3) out2p = relu(conv1x1(cat, wD2))   bf16 MMA, 3-stage cp.async ring
    k_gemm256_bf16<<<gGemm, 256, G256_SMEM>>>(wD2, p_catp, p_out2p);

    // 4) a1p = relu(conv3x3(out2, a1_w) + a1_b)   double-buffered pipeline
    k_conv3p<32><<<gConv, 256, CONV_SMEM>>>(p_out2p, a1_w, a1_b, p_a1p);

    // 5) a2p = relu(conv3x3(a1, a2_w) + a2_b)
    k_conv3p<16><<<gConv, 256, CONV_SMEM>>>(p_a1p, a2_w, a2_b, p_a2p);

    // 6) out = relu(x * sigmoid(a3_w . a2 + a3_b))
    k_final4<<<256, 256>>>(p_a2p, a3_w, a3_b, x, out);
}

// round 11
// speedup vs baseline: 1.8134x; 1.0152x over previous
#include <cuda_runtime.h>
#include <cuda_bf16.h>
#include <math.h>

#define HW      65536
#define BATCH   4

// ---------------- scratch (device globals; no allocation allowed) ----------
// pair channel pc <-> fp channels (c0, c1): c0 = (pc>>3)*16 + (pc&7), c1 = c0+8
__device__ unsigned g_out1p[(size_t)BATCH * 32  * HW];  //  34 MB
__device__ unsigned g_catp [(size_t)BATCH * 128 * HW];  // 134 MB (k2 = dir*32+pc)
__device__ unsigned g_out2p[(size_t)BATCH * 32  * HW];  //  34 MB
__device__ unsigned g_a1p  [(size_t)BATCH * 16  * HW];  //  17 MB
__device__ unsigned g_a2p  [(size_t)BATCH * 16  * HW];  //  17 MB

// ---------------- helpers ---------------------------------------------------
__device__ __forceinline__ unsigned f2tf(float f) {
    unsigned u;
    asm("cvt.rna.tf32.f32 %0, %1;" : "=r"(u) : "f"(f));
    return u;
}
__device__ __forceinline__ unsigned packbf(float hi, float lo) {
    unsigned r;
    asm("cvt.rn.bf16x2.f32 %0, %1, %2;" : "=r"(r) : "f"(hi), "f"(lo));
    return r;
}
__device__ __forceinline__ float2 unpackbf(unsigned u) {
    __nv_bfloat162 h = *reinterpret_cast<__nv_bfloat162*>(&u);
    return __bfloat1622float2(h);
}
__device__ __forceinline__ void cpasync16(void* dst, const void* src) {
    unsigned d = (unsigned)__cvta_generic_to_shared(dst);
    asm volatile("cp.async.cg.shared.global [%0], [%1], 16;" :: "r"(d), "l"(src));
}

#define MMA_TF32(c, a, b0, b1)                                              \
    asm volatile("mma.sync.aligned.m16n8k8.row.col.f32.tf32.tf32.f32 "      \
        "{%0,%1,%2,%3}, {%4,%5,%6,%7}, {%8,%9}, {%0,%1,%2,%3};"             \
        : "+f"((c)[0]), "+f"((c)[1]), "+f"((c)[2]), "+f"((c)[3])            \
        : "r"((a)[0]), "r"((a)[1]), "r"((a)[2]), "r"((a)[3]),               \
          "r"(b0), "r"(b1))

#define MMA_BF16(c, a, b0, b1)                                              \
    asm volatile("mma.sync.aligned.m16n8k16.row.col.f32.bf16.bf16.f32 "     \
        "{%0,%1,%2,%3}, {%4,%5,%6,%7}, {%8,%9}, {%0,%1,%2,%3};"             \
        : "+f"((c)[0]), "+f"((c)[1]), "+f"((c)[2]), "+f"((c)[3])            \
        : "r"((a)[0]), "r"((a)[1]), "r"((a)[2]), "r"((a)[3]),               \
          "r"(b0), "r"(b1))

// ---------------------------------------------------------------------------
// TF32 GEMM stage 1 (K=64): out1p(packed) = w_in @ x.
// Whole 64x256 fp32 X tile staged via one cp.async burst (overlapped with W
// tf32 conversion), single sync, then 8 k8 MMA chunks with cvt-on-read.
// Dynamic smem 85 KB -> 2 CTA/SM. grid (256,1,4).
// ---------------------------------------------------------------------------
#define G64_XS   (64 * 264)             // fp32 words
#define G64_WS   (64 * 68)              // tf32 words
#define G64_SMEM ((G64_XS + G64_WS) * 4)

__global__ __launch_bounds__(256, 2)
void k_gemm_tc64(const float* __restrict__ Wt, const float* __restrict__ X,
                 unsigned* __restrict__ Yp)
{
    extern __shared__ float dsm64[];
    float*    xs = dsm64;                          // [64][264] fp32
    unsigned* ws = (unsigned*)(dsm64 + G64_XS);    // [64][68]  tf32

    const int tid  = threadIdx.x;
    const int warp = tid >> 5;
    const int lane = tid & 31;
    const int n0   = blockIdx.x * 256;
    const int b    = blockIdx.z;
    const float* Xb = X  + (size_t)b * 64 * HW;
    unsigned*    Yb = Yp + (size_t)b * 32 * HW;

    const int mw = (warp & 1) * 32;
    const int nw = (warp >> 1) * 64;
    const int qt = lane >> 2;
    const int rt = lane & 3;

    // stage whole X tile (64 rows x 256 cols fp32) via cp.async
#pragma unroll
    for (int j = 0; j < 16; j++) {
        int idx = tid + j * 256;        // 0..4095
        int k   = idx >> 6;
        int c4  = (idx & 63) * 4;
        cpasync16(&xs[k * 264 + c4], Xb + (size_t)k * HW + n0 + c4);
    }
    asm volatile("cp.async.commit_group;");

    // stage W (64x64) -> tf32, overlapped with the async copies
#pragma unroll
    for (int i = 0; i < 16; i++) {
        int e = tid + i * 256;
        int m = e >> 6, k = e & 63;
        ws[m * 68 + k] = f2tf(Wt[m * 64 + k]);
    }
    asm volatile("cp.async.wait_group 0;");
    __syncthreads();

    float acc[2][8][4];
#pragma unroll
    for (int i = 0; i < 2; i++)
#pragma unroll
        for (int j = 0; j < 8; j++)
#pragma unroll
            for (int v = 0; v < 4; v++) acc[i][j][v] = 0.f;

#pragma unroll
    for (int kk = 0; kk < 8; kk++) {
        const int kb = kk * 8;
        unsigned a[2][4];
#pragma unroll
        for (int mt = 0; mt < 2; mt++) {
            int mr = mw + mt * 16 + qt;
            a[mt][0] = ws[mr * 68 + kb + rt];
            a[mt][1] = ws[(mr + 8) * 68 + kb + rt];
            a[mt][2] = ws[mr * 68 + kb + rt + 4];
            a[mt][3] = ws[(mr + 8) * 68 + kb + rt + 4];
        }
#pragma unroll
        for (int nt = 0; nt < 8; nt++) {
            int col = nw + nt * 8 + qt;
            unsigned b0 = f2tf(xs[(kb + rt) * 264 + col]);
            unsigned b1 = f2tf(xs[(kb + rt + 4) * 264 + col]);
            MMA_TF32(acc[0][nt], a[0], b0, b1);
            MMA_TF32(acc[1][nt], a[1], b0, b1);
        }
    }

    // epilogue: pack rows (mr, mr+8) -> pair channel pc = (mr>>4)*8 + qt
#pragma unroll
    for (int mt = 0; mt < 2; mt++) {
        int pc = ((mw >> 4) + mt) * 8 + qt;
#pragma unroll
        for (int nt = 0; nt < 8; nt++) {
            int col = n0 + nw + nt * 8 + rt * 2;
            uint2 u;
            u.x = packbf(acc[mt][nt][2], acc[mt][nt][0]);
            u.y = packbf(acc[mt][nt][3], acc[mt][nt][1]);
            *(uint2*)&Yb[(size_t)pc * HW + col] = u;
        }
    }
}

// ---------------------------------------------------------------------------
// 4-direction IRNN scans, one pass per block (fwd/bwd split => 2x parallelism).
// 512 blocks: [0,128) down, [128,256) up, [256,384) right, [384,512) left.
// ---------------------------------------------------------------------------
__global__ __launch_bounds__(256)
void k_scans4(const unsigned* __restrict__ srcp, unsigned* __restrict__ catp,
              const float* __restrict__ w_up, const float* __restrict__ b_up,
              const float* __restrict__ w_rt, const float* __restrict__ b_rt,
              const float* __restrict__ w_dn, const float* __restrict__ b_dn,
              const float* __restrict__ w_lt, const float* __restrict__ b_lt)
{
    const int dir = blockIdx.x >> 7;
    const int blk = blockIdx.x & 127;
    const int tid = threadIdx.x;
    const int pc  = blk & 31;
    const int b   = blk >> 5;
    const int c0  = ((pc >> 3) * 16) + (pc & 7);
    const int c1  = c0 + 8;

    const float *wv, *bv;
    int k2off; bool vert, fwd;
    if (dir == 0)      { wv = w_dn; bv = b_dn; k2off = 64; vert = true;  fwd = true;  }
    else if (dir == 1) { wv = w_up; bv = b_up; k2off = 0;  vert = true;  fwd = false; }
    else if (dir == 2) { wv = w_rt; bv = b_rt; k2off = 32; vert = false; fwd = true;  }
    else               { wv = w_lt; bv = b_lt; k2off = 96; vert = false; fwd = false; }

    const float W0 = wv[c0], W1 = wv[c1], B0 = bv[c0], B1 = bv[c1];

    int off  = vert ? tid : tid * 256;
    int step = vert ? 256 : 1;
    if (!fwd) { off += step * 255; step = -step; }

    const unsigned* sp = srcp + (((size_t)b * 32 + pc) << 16) + off;
    unsigned*       dp = catp + (((size_t)b * 128 + k2off + pc) << 16) + off;

    float h0 = 0.f, h1 = 0.f;
    unsigned v = *sp;
    sp += step;
#pragma unroll 8
    for (int i = 0; i < 256; i++) {
        unsigned vn = 0;
        if (i < 255) vn = *sp;          // prefetch: independent of the fma chain
        sp += step;
        float2 f = unpackbf(v);
        h0 = fmaxf(fmaf(W0, h0, f.x + B0), 0.f);
        h1 = fmaxf(fmaf(W1, h1, f.y + B1), 0.f);
        *dp = packbf(h1, h0);
        dp += step;
        v = vn;
    }
}

// ---------------------------------------------------------------------------
// BF16 GEMM stage 3: out2p = relu(wD2 @ cat), K=256 (128 pairs).
// Full A resident in smem (stride 132, conflict-free), 3-stage cp.async ring
// for B (stride 264 -> conflict-free frag loads). Dynamic smem 84.5 KB.
// ---------------------------------------------------------------------------
#define G256_WS   (64 * 132)            // 8448 words
#define G256_XSLOT (16 * 264)           // 4224 words
#define G256_SMEM ((G256_WS + 3 * G256_XSLOT) * 4)

__global__ __launch_bounds__(256)
void k_gemm256_bf16(const float* __restrict__ Wt, const unsigned* __restrict__ Xp,
                    unsigned* __restrict__ Yp)
{
    extern __shared__ unsigned dsm[];
    unsigned* wsf = dsm;                // [64][132]
    unsigned* xsp = dsm + G256_WS;      // 3 slots of [16][264]

    const int tid  = threadIdx.x;
    const int warp = tid >> 5;
    const int lane = tid & 31;
    const int n0   = blockIdx.x * 256;
    const int b    = blockIdx.z;
    const unsigned* Xb = Xp + (size_t)b * 128 * HW;
    unsigned*       Yb = Yp + (size_t)b * 32 * HW;

    const int nw = warp * 32;
    const int qt = lane >> 2;
    const int rt = lane & 3;

    // stage B chunks 0,1 first (overlaps with A packing below)
#pragma unroll
    for (int c = 0; c < 2; c++) {
#pragma unroll
        for (int j = 0; j < 4; j++) {
            int idx = tid + j * 256, row = idx >> 6, col4 = (idx & 63) * 4;
            cpasync16(&xsp[c * G256_XSLOT + row * 264 + col4],
                      Xb + (size_t)(c * 16 + row) * HW + n0 + col4);
        }
        asm volatile("cp.async.commit_group;");
    }

    // pack full A: wsf[m][l2] = bf16x2(Wt[m][c0], Wt[m][c0+8])
#pragma unroll
    for (int i = 0; i < 32; i++) {
        int e = tid + i * 256;
        int m = e >> 7, l2 = e & 127;
        int d2 = l2 >> 5, pcd = l2 & 31;
        int cc = d2 * 64 + ((pcd >> 3) * 16) + (pcd & 7);
        wsf[m * 132 + l2] = packbf(Wt[m * 256 + cc + 8], Wt[m * 256 + cc]);
    }

    float acc[4][4][4];
#pragma unroll
    for (int i = 0; i < 4; i++)
#pragma unroll
        for (int j = 0; j < 4; j++)
#pragma unroll
            for (int v = 0; v < 4; v++) acc[i][j][v] = 0.f;

    for (int kt = 0; kt < 8; kt++) {
        __syncthreads();                      // protect ring slot reuse
        if (kt + 2 < 8) {
            int sl = (kt + 2) % 3;
#pragma unroll
            for (int j = 0; j < 4; j++) {
                int idx = tid + j * 256, row = idx >> 6, col4 = (idx & 63) * 4;
                cpasync16(&xsp[sl * G256_XSLOT + row * 264 + col4],
                          Xb + (size_t)((kt + 2) * 16 + row) * HW + n0 + col4);
            }
            asm volatile("cp.async.commit_group;");
        }
        if (kt < 6)      asm volatile("cp.async.wait_group 2;");
        else if (kt == 6) asm volatile("cp.async.wait_group 1;");
        else              asm volatile("cp.async.wait_group 0;");
        __syncthreads();

        const unsigned* xc = xsp + (kt % 3) * G256_XSLOT;
        const int kg = kt * 16;
#pragma unroll
        for (int s = 0; s < 2; s++) {
            const int kb = s * 8;
            unsigned a[4][4];
#pragma unroll
            for (int mt = 0; mt < 4; mt++) {
                int m = mt * 16 + qt;
                int k2 = kg + kb + rt;
                a[mt][0] = wsf[m * 132 + k2];
                a[mt][1] = wsf[(m + 8) * 132 + k2];
                a[mt][2] = wsf[m * 132 + k2 + 4];
                a[mt][3] = wsf[(m + 8) * 132 + k2 + 4];
            }
#pragma unroll
            for (int nt = 0; nt < 4; nt++) {
                int col = nw + nt * 8 + qt;
                unsigned b0 = xc[(kb + rt) * 264 + col];
                unsigned b1 = xc[(kb + rt + 4) * 264 + col];
#pragma unroll
                for (int mt = 0; mt < 4; mt++)
                    MMA_BF16(acc[mt][nt], a[mt], b0, b1);
            }
        }
    }

    // epilogue: relu + pack rows (m, m+8) -> pc = mt*8 + qt
#pragma unroll
    for (int mt = 0; mt < 4; mt++) {
        int pc = mt * 8 + qt;
#pragma unroll
        for (int nt = 0; nt < 4; nt++) {
            int col = n0 + nw + nt * 8 + rt * 2;
            uint2 u;
            u.x = packbf(fmaxf(acc[mt][nt][2], 0.f), fmaxf(acc[mt][nt][0], 0.f));
            u.y = packbf(fmaxf(acc[mt][nt][3], 0.f), fmaxf(acc[mt][nt][1], 0.f));
            *(uint2*)&Yb[(size_t)pc * HW + col] = u;
        }
    }
}

// ---------------------------------------------------------------------------
// BF16 3x3 conv on packed pairs, double-buffered channel-chunk pipeline AND
// tap-level register double-buffering (fragments for tap t+1 loaded while
// tap t's MMAs issue). Dynamic smem 90.6 KB -> 2 CTA/SM. grid (128,1,4).
// ---------------------------------------------------------------------------
#define CONV_XSLOT (4 * 8 * 264)        // 8448 words
#define CONV_WSLOT (9 * 8 * 40)         // 2880 words
#define CONV_SMEM  ((2 * CONV_XSLOT + 2 * CONV_WSLOT) * 4)

template<int NPAIR>
__global__ __launch_bounds__(256, 2)
void k_conv3p(const unsigned* __restrict__ inp, const float* __restrict__ wt,
              const float* __restrict__ bias, unsigned* __restrict__ outp)
{
    constexpr int CI  = NPAIR * 2;
    constexpr int NCH = NPAIR / 8;

    extern __shared__ unsigned dsm[];
    unsigned* xsb = dsm;                       // 2 x CONV_XSLOT
    unsigned* wsb = dsm + 2 * CONV_XSLOT;      // 2 x CONV_WSLOT

    const int h0    = blockIdx.x * 2;
    const int b     = blockIdx.z;
    const int tid   = threadIdx.x;
    const int warp  = tid >> 5;
    const int lane  = tid & 31;
    const int rw    = warp >> 2;               // output row 0/1
    const int strip = (warp & 3) * 64;
    const int qt    = lane >> 2;
    const int rt    = lane & 3;

    const unsigned* inb = inp + (size_t)b * NPAIR * HW;

    // zero halo columns (cols 3 & 260) in both buffers, once
    if (tid < 128) {
        int buf = tid >> 6, rem = tid & 63;
        int side = rem >> 5, rr = (rem >> 3) & 3, i2 = rem & 7;
        xsb[buf * CONV_XSLOT + (rr * 8 + i2) * 264 + (side ? 260 : 3)] = 0u;
    }

    float acc[2][8][4];
#pragma unroll
    for (int i = 0; i < 2; i++)
#pragma unroll
        for (int j = 0; j < 8; j++)
#pragma unroll
            for (int v = 0; v < 4; v++) acc[i][j][v] = 0.f;

#define STAGE_X(CH, XD)                                                       \
    {                                                                         \
        unsigned* xd = (XD);                                                  \
        _Pragma("unroll")                                                     \
        for (int j = 0; j < 8; j++) {                                         \
            int e  = tid + j * 256;                                           \
            int i2 = e >> 8;                                                  \
            int r  = (e >> 6) & 3;                                            \
            int bk = e & 63;                                                  \
            int hh = h0 + r - 1;                                              \
            unsigned* dst = &xd[(r * 8 + i2) * 264 + 4 + bk * 4];             \
            if ((unsigned)hh < 256u)                                          \
                cpasync16(dst, inb + (size_t)((CH) * 8 + i2) * HW + hh * 256 + bk * 4); \
            else                                                              \
                *(uint4*)dst = make_uint4(0, 0, 0, 0);                        \
        }                                                                     \
        asm volatile("cp.async.commit_group;");                               \
    }

#define STAGE_W(CH, WD)                                                       \
    {                                                                         \
        unsigned* wd = (WD);                                                  \
        for (int e = tid; e < 9 * 8 * 32; e += 256) {                         \
            int tap = e >> 8;                                                 \
            int i2  = (e >> 5) & 7;                                           \
            int o   = e & 31;                                                 \
            int pg  = (CH) * 8 + i2;                                          \
            int cc  = ((pg >> 3) * 16) + (pg & 7);                            \
            const float* p = wt + ((size_t)o * CI + cc) * 9 + tap;            \
            wd[(tap * 8 + i2) * 40 + o] = packbf(p[72], p[0]);                \
        }                                                                     \
    }

// fragment loader for tap TAP into register buffer S (compile-time after unroll)
#define LOADFRAG(TAP, S)                                                      \
    {                                                                         \
        const int r_ = (TAP) / 3, c_ = (TAP) % 3;                             \
        const int ri_ = rw + r_;                                              \
        _Pragma("unroll")                                                     \
        for (int mt = 0; mt < 2; mt++) {                                      \
            int o = mt * 16 + qt;                                             \
            af[S][mt][0] = wc[((TAP) * 8 + rt) * 40 + o];                     \
            af[S][mt][1] = wc[((TAP) * 8 + rt) * 40 + o + 8];                 \
            af[S][mt][2] = wc[((TAP) * 8 + rt + 4) * 40 + o];                 \
            af[S][mt][3] = wc[((TAP) * 8 + rt + 4) * 40 + o + 8];             \
        }                                                                     \
        _Pragma("unroll")                                                     \
        for (int nt = 0; nt < 8; nt++) {                                      \
            int col = strip + nt * 8 + qt + c_ + 3;                           \
            bf[S][nt][0] = xc[(ri_ * 8 + rt) * 264 + col];                    \
            bf[S][nt][1] = xc[(ri_ * 8 + rt + 4) * 264 + col];                \
        }                                                                     \
    }

    // prologue: chunk 0
    STAGE_X(0, xsb + 0);
    STAGE_W(0, wsb + 0);

    for (int ch = 0; ch < NCH; ch++) {
        const int cur = ch & 1, nxt = cur ^ 1;
        __syncthreads();                        // protect nxt buffers (prev compute)
        if (ch + 1 < NCH) {
            STAGE_X(ch + 1, xsb + nxt * CONV_XSLOT);
            STAGE_W(ch + 1, wsb + nxt * CONV_WSLOT);
            asm volatile("cp.async.wait_group 1;");
        } else {
            asm volatile("cp.async.wait_group 0;");
        }
        __syncthreads();                        // cur buffers visible

        const unsigned* xc = xsb + cur * CONV_XSLOT;
        const unsigned* wc = wsb + cur * CONV_WSLOT;

        unsigned af[2][2][4];
        unsigned bf[2][8][2];
        LOADFRAG(0, 0);
#pragma unroll
        for (int tap = 0; tap < 9; tap++) {
            const int cb = tap & 1;
            if (tap < 8) LOADFRAG(tap + 1, cb ^ 1);   // prefetch next tap
#pragma unroll
            for (int nt = 0; nt < 8; nt++) {
                MMA_BF16(acc[0][nt], af[cb][0], bf[cb][nt][0], bf[cb][nt][1]);
                MMA_BF16(acc[1][nt], af[cb][1], bf[cb][nt][0], bf[cb][nt][1]);
            }
        }
    }
#undef STAGE_X
#undef STAGE_W
#undef LOADFRAG

    // epilogue: bias + relu, pack (o, o+8) -> pc = mt*8 + qt
    const int orow = (h0 + rw) * 256;
#pragma unroll
    for (int mt = 0; mt < 2; mt++) {
        int o   = mt * 16 + qt;
        int pc  = mt * 8 + qt;
        float bv0 = bias[o];
        float bv1 = bias[o + 8];
#pragma unroll
        for (int nt = 0; nt < 8; nt++) {
            int col = strip + nt * 8 + rt * 2;
            uint2 u;
            u.x = packbf(fmaxf(acc[mt][nt][2] + bv1, 0.f),
                         fmaxf(acc[mt][nt][0] + bv0, 0.f));
            u.y = packbf(fmaxf(acc[mt][nt][3] + bv1, 0.f),
                         fmaxf(acc[mt][nt][1] + bv0, 0.f));
            *(uint2*)&outp[((size_t)(b * 16 + pc)) * HW + orow + col] = u;
        }
    }
}

// ---------------------------------------------------------------------------
// Final: a = a3_w . a2 + a3_b ; weight = sigmoid(a) ; out = relu(x * weight)
// ---------------------------------------------------------------------------
__global__ __launch_bounds__(256)
void k_final4(const unsigned* __restrict__ a2p, const float* __restrict__ a3w,
              const float* __restrict__ a3b, const float* __restrict__ x,
              float* __restrict__ out)
{
    int t   = blockIdx.x * 256 + threadIdx.x;
    int b   = t >> 14;
    int hw  = (t & 16383) * 4;

    const unsigned* ab = a2p + ((size_t)b * 16) * HW + hw;
    float bv = a3b[0];
    float4 s = {bv, bv, bv, bv};
#pragma unroll
    for (int pc = 0; pc < 16; pc++) {
        int c0 = ((pc >> 3) * 16) + (pc & 7);
        float w0 = a3w[c0], w1 = a3w[c0 + 8];
        uint4 u = *(const uint4*)&ab[(size_t)pc * HW];
        float2 v0 = unpackbf(u.x), v1 = unpackbf(u.y);
        float2 v2 = unpackbf(u.z), v3 = unpackbf(u.w);
        s.x = fmaf(w0, v0.x, fmaf(w1, v0.y, s.x));
        s.y = fmaf(w0, v1.x, fmaf(w1, v1.y, s.y));
        s.z = fmaf(w0, v2.x, fmaf(w1, v2.y, s.z));
        s.w = fmaf(w0, v3.x, fmaf(w1, v3.y, s.w));
    }
    float4 g;
    g.x = 1.f / (1.f + expf(-s.x));
    g.y = 1.f / (1.f + expf(-s.y));
    g.z = 1.f / (1.f + expf(-s.z));
    g.w = 1.f / (1.f + expf(-s.w));

    const float* xb = x   + ((size_t)b * 64) * HW + hw;
    float*       ob = out + ((size_t)b * 64) * HW + hw;
#pragma unroll 8
    for (int c = 0; c < 64; c++) {
        float4 v = *(const float4*)&xb[(size_t)c * HW];
        float4 r;
        r.x = fmaxf(v.x * g.x, 0.f);
        r.y = fmaxf(v.y * g.y, 0.f);
        r.z = fmaxf(v.z * g.z, 0.f);
        r.w = fmaxf(v.w * g.w, 0.f);
        *(float4*)&ob[(size_t)c * HW] = r;
    }
}

// ---------------------------------------------------------------------------
extern "C" void kernel_launch(void* const* d_in, const int* in_sizes, int n_in,
                              void* d_out, int out_size)
{
    const float* x       = (const float*)d_in[0];
    const float* w_in    = (const float*)d_in[1];
    const float* w_up    = (const float*)d_in[2];
    const float* b_up    = (const float*)d_in[3];
    const float* w_right = (const float*)d_in[4];
    const float* b_right = (const float*)d_in[5];
    const float* w_down  = (const float*)d_in[6];
    const float* b_down  = (const float*)d_in[7];
    const float* w_left  = (const float*)d_in[8];
    const float* b_left  = (const float*)d_in[9];
    const float* wD2     = (const float*)d_in[10];
    const float* a1_w    = (const float*)d_in[11];
    const float* a1_b    = (const float*)d_in[12];
    const float* a2_w    = (const float*)d_in[13];
    const float* a2_b    = (const float*)d_in[14];
    const float* a3_w    = (const float*)d_in[15];
    const float* a3_b    = (const float*)d_in[16];
    float* out = (float*)d_out;

    unsigned *p_out1p, *p_catp, *p_out2p, *p_a1p, *p_a2p;
    cudaGetSymbolAddress((void**)&p_out1p, g_out1p);
    cudaGetSymbolAddress((void**)&p_catp,  g_catp);
    cudaGetSymbolAddress((void**)&p_out2p, g_out2p);
    cudaGetSymbolAddress((void**)&p_a1p,   g_a1p);
    cudaGetSymbolAddress((void**)&p_a2p,   g_a2p);

    // opt-in to >48KB dynamic smem (attribute set is idempotent, capture-safe)
    cudaFuncSetAttribute(k_gemm_tc64,
                         cudaFuncAttributeMaxDynamicSharedMemorySize, G64_SMEM);
    cudaFuncSetAttribute(k_gemm256_bf16,
                         cudaFuncAttributeMaxDynamicSharedMemorySize, G256_SMEM);
    cudaFuncSetAttribute(k_conv3p<32>,
                         cudaFuncAttributeMaxDynamicSharedMemorySize, CONV_SMEM);
    cudaFuncSetAttribute(k_conv3p<16>,
                         cudaFuncAttributeMaxDynamicSharedMemorySize, CONV_SMEM);

    dim3 gGemm(HW / 256, 1, BATCH);      // (256,1,4)
    dim3 gConv(128, 1, BATCH);

    // 1) out1p = conv1x1(x, w_in)   (TF32 MMA, cp.async whole-tile staging)
    k_gemm_tc64<<<gGemm, 256, G64_SMEM>>>(w_in, x, p_out1p);

    // 2) 4-direction scans, fwd/bwd split (512 independent blocks)
    k_scans4<<<512, 256>>>(p_out1p, p_catp,
                           w_up, b_up, w_right, b_right,
                           w_down, b_down, w_left, b_left);

    // 3) out2p = relu(conv1x1(cat, wD2))   bf16 MMA, 3-stage cp.async ring
    k_gemm256_bf16<<<gGemm, 256, G256_SMEM>>>(wD2, p_catp, p_out2p);

    // 4) a1p = relu(conv3x3(out2, a1_w) + a1_b)   chunk + tap pipelined
    k_conv3p<32><<<gConv, 256, CONV_SMEM>>>(p_out2p, a1_w, a1_b, p_a1p);

    // 5) a2p = relu(conv3x3(a1, a2_w) + a2_b)
    k_conv3p<16><<<gConv, 256, CONV_SMEM>>>(p_a1p, a2_w, a2_b, p_a2p);

    // 6) out = relu(x * sigmoid(a3_w . a2 + a3_b))
    k_final4<<<256, 256>>>(p_a2p, a3_w, a3_b, x, out);
}